// round 1
// baseline (speedup 1.0000x reference)
#include <cuda_runtime.h>
#include <math.h>

// Problem constants
#define NB    4
#define NSEQ  1568
#define CDIM  1024
#define NH    16
#define HD    64
#define M_TOT (NB*NSEQ)          // 6272
#define QKV_OUT (3*CDIM)         // 3072
#define NKT   ((NSEQ+63)/64)     // 25 key tiles / query tiles

// Scratch (device globals — no allocation allowed)
__device__ float g_q[NB*NH*NSEQ*HD];
__device__ float g_k[NB*NH*NSEQ*HD];
__device__ float g_v[NB*NH*NSEQ*HD];
__device__ float g_attn[M_TOT*CDIM];

// ---------------------------------------------------------------------------
// Tiled SGEMM:  out[m, o] = sum_k A[m,k] * W[o,k]   (W row-major [o][k])
// BM=BN=64, BK=16, 256 threads, 4x4 per-thread tile.
// EPI==0: scatter into g_q/g_k/g_v (QKV projection, per RoPEAttention layout)
// EPI==1: A is ignored (reads g_attn), adds bias, writes dense out [M,1024]
// ---------------------------------------------------------------------------
template<int EPI>
__global__ __launch_bounds__(256) void gemm_kernel(const float* __restrict__ A,
                                                   const float* __restrict__ W,
                                                   const float* __restrict__ bias,
                                                   float* __restrict__ out)
{
    __shared__ float Xs[16][64];   // [k][m]
    __shared__ float Ws[16][64];   // [k][o]
    const int t  = threadIdx.x;
    const int tx = t & 15;
    const int ty = t >> 4;
    const int m0 = blockIdx.y * 64;
    const int o0 = blockIdx.x * 64;

    const int lr = t >> 2;          // 0..63 (tile row)
    const int lc = (t & 3) * 4;     // 0,4,8,12 (k chunk)

    const float* Asrc = (EPI == 0) ? A : g_attn;
    const float* Ap = Asrc + (size_t)(m0 + lr) * CDIM + lc;
    const float* Wp = W    + (size_t)(o0 + lr) * CDIM + lc;

    float4 xa = *(const float4*)Ap;
    float4 wa = *(const float4*)Wp;

    float c[4][4] = {};

    #pragma unroll 1
    for (int kt = 0; kt < CDIM / 16; kt++) {
        __syncthreads();
        Xs[lc+0][lr] = xa.x; Xs[lc+1][lr] = xa.y;
        Xs[lc+2][lr] = xa.z; Xs[lc+3][lr] = xa.w;
        Ws[lc+0][lr] = wa.x; Ws[lc+1][lr] = wa.y;
        Ws[lc+2][lr] = wa.z; Ws[lc+3][lr] = wa.w;
        __syncthreads();
        if (kt + 1 < CDIM / 16) {
            xa = *(const float4*)(Ap + (kt + 1) * 16);
            wa = *(const float4*)(Wp + (kt + 1) * 16);
        }
        #pragma unroll
        for (int kk = 0; kk < 16; kk++) {
            float4 a4 = *(const float4*)&Xs[kk][ty * 4];
            float4 b4 = *(const float4*)&Ws[kk][tx * 4];
            c[0][0] += a4.x*b4.x; c[0][1] += a4.x*b4.y; c[0][2] += a4.x*b4.z; c[0][3] += a4.x*b4.w;
            c[1][0] += a4.y*b4.x; c[1][1] += a4.y*b4.y; c[1][2] += a4.y*b4.z; c[1][3] += a4.y*b4.w;
            c[2][0] += a4.z*b4.x; c[2][1] += a4.z*b4.y; c[2][2] += a4.z*b4.z; c[2][3] += a4.z*b4.w;
            c[3][0] += a4.w*b4.x; c[3][1] += a4.w*b4.y; c[3][2] += a4.w*b4.z; c[3][3] += a4.w*b4.w;
        }
    }

    if (EPI == 0) {
        // Column tile o0 maps to a single (s, h); cols within tile = head dim d.
        const int s = o0 >> 10;          // 0,1,2 => q,k,v
        const int h = (o0 >> 6) & 15;
        float* dst = (s == 0) ? g_q : (s == 1) ? g_k : g_v;
        #pragma unroll
        for (int i = 0; i < 4; i++) {
            const int m = m0 + ty * 4 + i;
            const int b = m / NSEQ;
            const int n = m - b * NSEQ;
            float* p = dst + (((size_t)(b * NH + h)) * NSEQ + n) * HD + tx * 4;
            float4 v4 = make_float4(c[i][0], c[i][1], c[i][2], c[i][3]);
            *(float4*)p = v4;
        }
    } else {
        #pragma unroll
        for (int i = 0; i < 4; i++) {
            const int m = m0 + ty * 4 + i;
            const int o = o0 + tx * 4;
            float4 bb = *(const float4*)(bias + o);
            float4 v4 = make_float4(c[i][0] + bb.x, c[i][1] + bb.y,
                                    c[i][2] + bb.z, c[i][3] + bb.w);
            *(float4*)(out + (size_t)m * CDIM + o) = v4;
        }
    }
}

// ---------------------------------------------------------------------------
// RoPE (3-axis factorized, matching the reference's interleaved-pair /
// half-concat cos-sin indexing exactly). In-place on g_q and g_k.
// One thread per pair per tensor: total = 2 * B*H*N * 30 pairs.
// ---------------------------------------------------------------------------
__global__ void rope_kernel()
{
    const int total = 2 * NB * NH * NSEQ * 30;
    int i = blockIdx.x * blockDim.x + threadIdx.x;
    if (i >= total) return;

    const int p30  = i % 30;
    int rest       = i / 30;
    const int bhn  = rest % (NB * NH * NSEQ);
    const int tsel = rest / (NB * NH * NSEQ);

    const int n  = bhn % NSEQ;
    const int bh = bhn / NSEQ;

    const int a = p30 / 10;      // axis: 0 frame, 1 height, 2 width
    const int p = p30 % 10;      // pair within 20-dim block

    const int rem = n % 196;
    float pos;
    if (a == 0)      pos = (float)(n / 196);
    else if (a == 1) pos = (float)(rem / 14);
    else             pos = (float)(rem % 14);

    const int d0 = a * 20 + 2 * p;
    const int f0 = (2 * p) % 10;
    const int f1 = (2 * p + 1) % 10;
    // omega_f = 10000^{-f/10}
    const float LOG1E4 = 9.210340371976184f;
    const float w0 = expf(-(float)f0 * 0.1f * LOG1E4);
    const float w1 = expf(-(float)f1 * 0.1f * LOG1E4);

    float s0, c0, s1, c1;
    sincosf(pos * w0, &s0, &c0);
    sincosf(pos * w1, &s1, &c1);

    float* buf = tsel ? g_k : g_q;
    const size_t base = ((size_t)bh * NSEQ + n) * HD;
    const float x0 = buf[base + d0];
    const float x1 = buf[base + d0 + 1];
    buf[base + d0]     = x0 * c0 - x1 * s0;
    buf[base + d0 + 1] = x1 * c1 + x0 * s1;
}

// ---------------------------------------------------------------------------
// Flash attention, fp32. Block = (64 q rows) x one (b,h). 256 threads.
// Dynamic smem: Qs[64][68], KV[64][68] (K transposed then V), Ps[64][68].
// Online softmax. Writes to g_attn in [B, N, C] layout for the proj GEMM.
// ---------------------------------------------------------------------------
#define SMS 68
__global__ __launch_bounds__(256) void attn_kernel()
{
    extern __shared__ float sm[];
    float* Qs = sm;                 // [row][d]     stride 68
    float* KV = sm + 64 * SMS;      // K: [d][key] / V: [key][d]
    float* Ps = KV + 64 * SMS;      // [row][key]

    const int t  = threadIdx.x;
    const int tx = t & 15;
    const int ty = t >> 4;
    const int r0 = ty * 4;
    const int c0 = tx * 4;

    const int bh = blockIdx.y;
    const int q0 = blockIdx.x * 64;

    const float* Qp = g_q + (size_t)bh * NSEQ * HD;
    const float* Kp = g_k + (size_t)bh * NSEQ * HD;
    const float* Vp = g_v + (size_t)bh * NSEQ * HD;

    const int lrow = t >> 4;        // 0..15
    const int lcol = (t & 15) * 4;  // 0..60

    // Load Q tile (zero-pad rows beyond NSEQ)
    #pragma unroll
    for (int rep = 0; rep < 4; rep++) {
        const int r  = rep * 16 + lrow;
        const int gn = q0 + r;
        float4 v = (gn < NSEQ) ? *(const float4*)(Qp + (size_t)gn * HD + lcol)
                               : make_float4(0.f, 0.f, 0.f, 0.f);
        *(float4*)&Qs[r * SMS + lcol] = v;
    }

    float m_[4], l_[4], acc[4][4];
    #pragma unroll
    for (int i = 0; i < 4; i++) {
        m_[i] = -3.0e38f; l_[i] = 0.f;
        #pragma unroll
        for (int j = 0; j < 4; j++) acc[i][j] = 0.f;
    }

    #pragma unroll 1
    for (int kt = 0; kt < NKT; kt++) {
        const int k0 = kt * 64;
        const int kn = min(64, NSEQ - k0);

        __syncthreads();   // previous GEMM2 done with KV(V) and Ps
        // Load K tile, transposed: KV[d][key]
        #pragma unroll
        for (int rep = 0; rep < 4; rep++) {
            const int key = rep * 16 + lrow;
            float4 kv = (key < kn) ? *(const float4*)(Kp + (size_t)(k0 + key) * HD + lcol)
                                   : make_float4(0.f, 0.f, 0.f, 0.f);
            KV[(lcol + 0) * SMS + key] = kv.x;
            KV[(lcol + 1) * SMS + key] = kv.y;
            KV[(lcol + 2) * SMS + key] = kv.z;
            KV[(lcol + 3) * SMS + key] = kv.w;
        }
        __syncthreads();

        // S = Q K^T (rows r0.., keys c0..)
        float s[4][4] = {};
        #pragma unroll 16
        for (int d = 0; d < 64; d++) {
            const float qa0 = Qs[(r0 + 0) * SMS + d];
            const float qa1 = Qs[(r0 + 1) * SMS + d];
            const float qa2 = Qs[(r0 + 2) * SMS + d];
            const float qa3 = Qs[(r0 + 3) * SMS + d];
            const float4 kb = *(const float4*)&KV[d * SMS + c0];
            s[0][0] += qa0*kb.x; s[0][1] += qa0*kb.y; s[0][2] += qa0*kb.z; s[0][3] += qa0*kb.w;
            s[1][0] += qa1*kb.x; s[1][1] += qa1*kb.y; s[1][2] += qa1*kb.z; s[1][3] += qa1*kb.w;
            s[2][0] += qa2*kb.x; s[2][1] += qa2*kb.y; s[2][2] += qa2*kb.z; s[2][3] += qa2*kb.w;
            s[3][0] += qa3*kb.x; s[3][1] += qa3*kb.y; s[3][2] += qa3*kb.z; s[3][3] += qa3*kb.w;
        }

        const float scale = 0.125f;   // 64^-0.5
        #pragma unroll
        for (int i = 0; i < 4; i++) {
            #pragma unroll
            for (int j = 0; j < 4; j++) {
                s[i][j] *= scale;
                if (c0 + j >= kn) s[i][j] = -1.0e30f;
            }
        }

        // Online softmax per row (reduce across the 16-lane tx group)
        #pragma unroll
        for (int i = 0; i < 4; i++) {
            float rm = fmaxf(fmaxf(s[i][0], s[i][1]), fmaxf(s[i][2], s[i][3]));
            #pragma unroll
            for (int o = 8; o >= 1; o >>= 1)
                rm = fmaxf(rm, __shfl_xor_sync(0xffffffffu, rm, o));
            const float mn = fmaxf(m_[i], rm);
            const float al = __expf(m_[i] - mn);
            m_[i] = mn;
            float rs = 0.f;
            #pragma unroll
            for (int j = 0; j < 4; j++) {
                s[i][j] = __expf(s[i][j] - mn);
                rs += s[i][j];
            }
            #pragma unroll
            for (int o = 8; o >= 1; o >>= 1)
                rs += __shfl_xor_sync(0xffffffffu, rs, o);
            l_[i] = l_[i] * al + rs;
            #pragma unroll
            for (int j = 0; j < 4; j++) acc[i][j] *= al;
        }

        __syncthreads();   // everyone done reading KV(K)

        // Write P tile, load V tile
        #pragma unroll
        for (int i = 0; i < 4; i++)
            #pragma unroll
            for (int j = 0; j < 4; j++)
                Ps[(r0 + i) * SMS + c0 + j] = s[i][j];

        #pragma unroll
        for (int rep = 0; rep < 4; rep++) {
            const int key = rep * 16 + lrow;
            float4 vv = (key < kn) ? *(const float4*)(Vp + (size_t)(k0 + key) * HD + lcol)
                                   : make_float4(0.f, 0.f, 0.f, 0.f);
            *(float4*)&KV[key * SMS + lcol] = vv;
        }
        __syncthreads();

        // O += P V  (rows r0.., d-cols c0..)
        #pragma unroll 16
        for (int k = 0; k < 64; k++) {
            const float p0 = Ps[(r0 + 0) * SMS + k];
            const float p1 = Ps[(r0 + 1) * SMS + k];
            const float p2 = Ps[(r0 + 2) * SMS + k];
            const float p3 = Ps[(r0 + 3) * SMS + k];
            const float4 vv = *(const float4*)&KV[k * SMS + c0];
            acc[0][0] += p0*vv.x; acc[0][1] += p0*vv.y; acc[0][2] += p0*vv.z; acc[0][3] += p0*vv.w;
            acc[1][0] += p1*vv.x; acc[1][1] += p1*vv.y; acc[1][2] += p1*vv.z; acc[1][3] += p1*vv.w;
            acc[2][0] += p2*vv.x; acc[2][1] += p2*vv.y; acc[2][2] += p2*vv.z; acc[2][3] += p2*vv.w;
            acc[3][0] += p3*vv.x; acc[3][1] += p3*vv.y; acc[3][2] += p3*vv.z; acc[3][3] += p3*vv.w;
        }
    }

    // Epilogue: write [B, N, C] for the projection GEMM
    const int b = bh >> 4;
    const int h = bh & 15;
    #pragma unroll
    for (int i = 0; i < 4; i++) {
        const int gn = q0 + r0 + i;
        if (gn < NSEQ) {
            const float inv = 1.0f / l_[i];
            float4 v4 = make_float4(acc[i][0]*inv, acc[i][1]*inv, acc[i][2]*inv, acc[i][3]*inv);
            *(float4*)(g_attn + ((size_t)b * NSEQ + gn) * CDIM + h * HD + c0) = v4;
        }
    }
}

// ---------------------------------------------------------------------------
extern "C" void kernel_launch(void* const* d_in, const int* in_sizes, int n_in,
                              void* d_out, int out_size)
{
    const float* x     = (const float*)d_in[0];
    const float* Wqkv  = (const float*)d_in[1];
    const float* Wproj = (const float*)d_in[2];
    const float* bproj = (const float*)d_in[3];
    float* out = (float*)d_out;

    const int attn_smem = 3 * 64 * SMS * (int)sizeof(float);   // 52224 B
    cudaFuncSetAttribute(attn_kernel,
                         cudaFuncAttributeMaxDynamicSharedMemorySize, attn_smem);

    // 1) QKV projection, scattered into g_q/g_k/g_v [B,H,N,D]
    gemm_kernel<0><<<dim3(QKV_OUT / 64, M_TOT / 64), 256>>>(x, Wqkv, nullptr, nullptr);

    // 2) RoPE in place on q, k
    const int rope_total = 2 * NB * NH * NSEQ * 30;
    rope_kernel<<<(rope_total + 255) / 256, 256>>>();

    // 3) Attention -> g_attn [B,N,C]
    attn_kernel<<<dim3(NKT, NB * NH), 256, attn_smem>>>();

    // 4) Output projection + bias -> d_out
    gemm_kernel<1><<<dim3(CDIM / 64, M_TOT / 64), 256>>>(nullptr, Wproj, bproj, out);
}

// round 6
// speedup vs baseline: 1.6407x; 1.6407x over previous
#include <cuda_runtime.h>
#include <cuda_bf16.h>
#include <math.h>
#include <stdint.h>

// Problem constants
#define NB    4
#define NSEQ  1568
#define CDIM  1024
#define NH    16
#define HD    64
#define M_TOT (NB*NSEQ)          // 6272
#define QKV_OUT (3*CDIM)         // 3072
#define NKT   ((NSEQ+63)/64)     // 25

// Scratch (device globals — no allocation allowed)
__device__ float g_q[NB*NH*NSEQ*HD];
__device__ float g_k[NB*NH*NSEQ*HD];
__device__ float g_v[NB*NH*NSEQ*HD];
__device__ float g_attn[M_TOT*CDIM];

// ===========================================================================
// Warp-MMA helpers (compute_103-safe: mma.sync + ldmatrix, sm_80 features)
// ===========================================================================
__device__ __forceinline__ uint32_t smem_u32(const void* p) {
    uint32_t a;
    asm("{ .reg .u64 t; cvta.to.shared.u64 t, %1; cvt.u32.u64 %0, t; }"
        : "=r"(a) : "l"(p));
    return a;
}

#define LDMX4(r0, r1, r2, r3, addr) \
    asm volatile("ldmatrix.sync.aligned.m8n8.x4.shared.b16 {%0,%1,%2,%3}, [%4];" \
        : "=r"(r0), "=r"(r1), "=r"(r2), "=r"(r3) : "r"(addr))

#define MMA16816(d, a, b0, b1) \
    asm volatile("mma.sync.aligned.m16n8k16.row.col.f32.bf16.bf16.f32 " \
        "{%0,%1,%2,%3}, {%4,%5,%6,%7}, {%8,%9}, {%0,%1,%2,%3};" \
        : "+f"((d)[0]), "+f"((d)[1]), "+f"((d)[2]), "+f"((d)[3]) \
        : "r"((a)[0]), "r"((a)[1]), "r"((a)[2]), "r"((a)[3]), "r"(b0), "r"(b1))

// convert float4 -> 4 bf16 hi (uint2) + 4 bf16 lo (uint2)
__device__ __forceinline__ void cvt4_hl(float4 f, uint2& hi, uint2& lo) {
    float xs[4] = {f.x, f.y, f.z, f.w};
    uint32_t h[2], l[2];
    #pragma unroll
    for (int i = 0; i < 2; i++) {
        float a = xs[2*i], b = xs[2*i+1];
        __nv_bfloat16 ha = __float2bfloat16_rn(a);
        __nv_bfloat16 hb = __float2bfloat16_rn(b);
        float ra = a - __bfloat162float(ha);
        float rb = b - __bfloat162float(hb);
        __nv_bfloat16 la = __float2bfloat16_rn(ra);
        __nv_bfloat16 lb = __float2bfloat16_rn(rb);
        h[i] = (uint32_t)__bfloat16_as_ushort(ha) | ((uint32_t)__bfloat16_as_ushort(hb) << 16);
        l[i] = (uint32_t)__bfloat16_as_ushort(la) | ((uint32_t)__bfloat16_as_ushort(lb) << 16);
    }
    hi = make_uint2(h[0], h[1]);
    lo = make_uint2(l[0], l[1]);
}

// ===========================================================================
// bf16 3-term-split GEMM via mma.sync:
//   out[m,o] = sum_k A[m,k] * W[o,k]
//   CTA 128x128, BK=16, 8 warps (2x4), warp tile 64x32.
//   SMEM: [stage][hi/lo] 128x16 tiles, row stride 24 bf16 (ldmatrix
//   conflict-free: 48B-stride rows land on distinct 16B banks mod 128B).
//   EPI==0: A = x, scatter into g_q/g_k/g_v
//   EPI==1: A = g_attn, add bias, dense out [M,1024]
// ===========================================================================
#define ASTR 24
#define NCH  (CDIM / 16)   // 64 chunks

template<int EPI>
__global__ __launch_bounds__(256, 2)
void gemm_mma(const float* __restrict__ A, const float* __restrict__ W,
              const float* __restrict__ bias, float* __restrict__ out)
{
    __shared__ __align__(16) uint16_t smA[2][2][128 * ASTR];  // [stage][hi/lo]
    __shared__ __align__(16) uint16_t smB[2][2][128 * ASTR];

    const int t    = threadIdx.x;
    const int lane = t & 31;
    const int w    = t >> 5;
    const int warpM = w >> 2;       // 0..1
    const int warpN = w & 3;        // 0..3
    const int m0 = blockIdx.y * 128;
    const int o0 = blockIdx.x * 128;

    const float* Asrc = (EPI == 0) ? A : g_attn;
    const int lrow = t >> 1;          // 0..127
    const int lco  = (t & 1) * 8;     // 0 or 8
    const float* Ap = Asrc + (size_t)(m0 + lrow) * CDIM + lco;
    const float* Wp = W    + (size_t)(o0 + lrow) * CDIM + lco;

    // ldmatrix source offsets (bf16 elements) within a [128][ASTR] matrix
    const int aR = warpM * 64;
    const uint32_t aFragOff = (uint32_t)(( (lane & 15) ) * ASTR + (lane >> 4) * 8);
    const uint32_t bRow  = (uint32_t)((lane & 7) + ((lane >> 4) << 3));
    const uint32_t bKoff = (uint32_t)(((lane >> 3) & 1) * 8);
    const int bN = warpN * 32;

    float acc[4][4][4];
    #pragma unroll
    for (int i = 0; i < 4; i++)
        #pragma unroll
        for (int j = 0; j < 4; j++)
            #pragma unroll
            for (int r = 0; r < 4; r++) acc[i][j][r] = 0.f;

    // prefetch chunk 0
    float4 pa0 = *(const float4*)(Ap + 0);
    float4 pa1 = *(const float4*)(Ap + 4);
    float4 pb0 = *(const float4*)(Wp + 0);
    float4 pb1 = *(const float4*)(Wp + 4);

    #pragma unroll 1
    for (int kc = 0; kc < NCH; kc++) {
        const int buf = kc & 1;

        // store prefetched chunk (convert to hi/lo bf16)
        {
            uint2 hi, lo;
            uint16_t* ah = &smA[buf][0][lrow * ASTR + lco];
            uint16_t* al = &smA[buf][1][lrow * ASTR + lco];
            cvt4_hl(pa0, hi, lo);
            *(uint2*)ah = hi;  *(uint2*)al = lo;
            cvt4_hl(pa1, hi, lo);
            *(uint2*)(ah + 4) = hi;  *(uint2*)(al + 4) = lo;

            uint16_t* bh = &smB[buf][0][lrow * ASTR + lco];
            uint16_t* bl = &smB[buf][1][lrow * ASTR + lco];
            cvt4_hl(pb0, hi, lo);
            *(uint2*)bh = hi;  *(uint2*)bl = lo;
            cvt4_hl(pb1, hi, lo);
            *(uint2*)(bh + 4) = hi;  *(uint2*)(bl + 4) = lo;
        }
        __syncthreads();

        // prefetch next chunk
        if (kc + 1 < NCH) {
            const float* An = Ap + (kc + 1) * 16;
            const float* Wn = Wp + (kc + 1) * 16;
            pa0 = *(const float4*)(An + 0);
            pa1 = *(const float4*)(An + 4);
            pb0 = *(const float4*)(Wn + 0);
            pb1 = *(const float4*)(Wn + 4);
        }

        // compute: 3 terms (Ah*Bh, Ah*Bl, Al*Bh)
        #pragma unroll
        for (int term = 0; term < 3; term++) {
            const uint16_t* Ab = smA[buf][term == 2 ? 1 : 0];
            const uint16_t* Bb = smB[buf][term == 1 ? 1 : 0];

            uint32_t af[4][4];
            #pragma unroll
            for (int mt = 0; mt < 4; mt++) {
                uint32_t addr = smem_u32(Ab + (aR + mt * 16) * ASTR) + aFragOff * 2;
                LDMX4(af[mt][0], af[mt][1], af[mt][2], af[mt][3], addr);
            }
            uint32_t bf[4][2];
            #pragma unroll
            for (int ntp = 0; ntp < 2; ntp++) {
                uint32_t addr = smem_u32(Bb + (bN + ntp * 16 + bRow) * ASTR + bKoff);
                LDMX4(bf[2*ntp][0], bf[2*ntp][1], bf[2*ntp+1][0], bf[2*ntp+1][1], addr);
            }
            #pragma unroll
            for (int mt = 0; mt < 4; mt++)
                #pragma unroll
                for (int nt = 0; nt < 4; nt++)
                    MMA16816(acc[mt][nt], af[mt], bf[nt][0], bf[nt][1]);
        }
    }

    // Epilogue
    const int lr = lane >> 2;
    const int lc = (lane & 3) * 2;
    #pragma unroll
    for (int mt = 0; mt < 4; mt++) {
        #pragma unroll
        for (int nt = 0; nt < 4; nt++) {
            const int o = o0 + warpN * 32 + nt * 8 + lc;
            #pragma unroll
            for (int half = 0; half < 2; half++) {
                const int m = m0 + warpM * 64 + mt * 16 + lr + half * 8;
                float2 v = make_float2(acc[mt][nt][half * 2], acc[mt][nt][half * 2 + 1]);
                if (EPI == 0) {
                    const int s  = o >> 10;
                    const int h  = (o >> 6) & 15;
                    const int d0 = o & 63;
                    const int b  = m / NSEQ;
                    const int n  = m - b * NSEQ;
                    float* dst = (s == 0 ? g_q : s == 1 ? g_k : g_v)
                                 + (((size_t)(b * NH + h)) * NSEQ + n) * HD + d0;
                    *(float2*)dst = v;
                } else {
                    v.x += bias[o];
                    v.y += bias[o + 1];
                    *(float2*)(out + (size_t)m * CDIM + o) = v;
                }
            }
        }
    }
}

// ---------------------------------------------------------------------------
// RoPE (unchanged, matches reference's interleaved-pair indexing exactly)
// ---------------------------------------------------------------------------
__global__ void rope_kernel()
{
    const int total = 2 * NB * NH * NSEQ * 30;
    int i = blockIdx.x * blockDim.x + threadIdx.x;
    if (i >= total) return;

    const int p30  = i % 30;
    int rest       = i / 30;
    const int bhn  = rest % (NB * NH * NSEQ);
    const int tsel = rest / (NB * NH * NSEQ);

    const int n  = bhn % NSEQ;
    const int bh = bhn / NSEQ;

    const int a = p30 / 10;
    const int p = p30 % 10;

    const int rem = n % 196;
    float pos;
    if (a == 0)      pos = (float)(n / 196);
    else if (a == 1) pos = (float)(rem / 14);
    else             pos = (float)(rem % 14);

    const int d0 = a * 20 + 2 * p;
    const int f0 = (2 * p) % 10;
    const int f1 = (2 * p + 1) % 10;
    const float LOG1E4 = 9.210340371976184f;
    const float w0 = expf(-(float)f0 * 0.1f * LOG1E4);
    const float w1 = expf(-(float)f1 * 0.1f * LOG1E4);

    float s0, c0, s1, c1;
    sincosf(pos * w0, &s0, &c0);
    sincosf(pos * w1, &s1, &c1);

    float* buf = tsel ? g_k : g_q;
    const size_t base = ((size_t)bh * NSEQ + n) * HD;
    const float x0 = buf[base + d0];
    const float x1 = buf[base + d0 + 1];
    buf[base + d0]     = x0 * c0 - x1 * s0;
    buf[base + d0 + 1] = x1 * c1 + x0 * s1;
}

// ---------------------------------------------------------------------------
// Flash attention, fp32 SIMT (unchanged this round)
// ---------------------------------------------------------------------------
#define SMS 68
__global__ __launch_bounds__(256) void attn_kernel()
{
    extern __shared__ float smf[];
    float* Qs = smf;
    float* KV = smf + 64 * SMS;
    float* Ps = KV + 64 * SMS;

    const int t  = threadIdx.x;
    const int tx = t & 15;
    const int ty = t >> 4;
    const int r0 = ty * 4;
    const int c0 = tx * 4;

    const int bh = blockIdx.y;
    const int q0 = blockIdx.x * 64;

    const float* Qp = g_q + (size_t)bh * NSEQ * HD;
    const float* Kp = g_k + (size_t)bh * NSEQ * HD;
    const float* Vp = g_v + (size_t)bh * NSEQ * HD;

    const int lrow = t >> 4;
    const int lcol = (t & 15) * 4;

    #pragma unroll
    for (int rep = 0; rep < 4; rep++) {
        const int r  = rep * 16 + lrow;
        const int gn = q0 + r;
        float4 v = (gn < NSEQ) ? *(const float4*)(Qp + (size_t)gn * HD + lcol)
                               : make_float4(0.f, 0.f, 0.f, 0.f);
        *(float4*)&Qs[r * SMS + lcol] = v;
    }

    float m_[4], l_[4], acc[4][4];
    #pragma unroll
    for (int i = 0; i < 4; i++) {
        m_[i] = -3.0e38f; l_[i] = 0.f;
        #pragma unroll
        for (int j = 0; j < 4; j++) acc[i][j] = 0.f;
    }

    #pragma unroll 1
    for (int kt = 0; kt < NKT; kt++) {
        const int k0 = kt * 64;
        const int kn = min(64, NSEQ - k0);

        __syncthreads();
        #pragma unroll
        for (int rep = 0; rep < 4; rep++) {
            const int key = rep * 16 + lrow;
            float4 kv = (key < kn) ? *(const float4*)(Kp + (size_t)(k0 + key) * HD + lcol)
                                   : make_float4(0.f, 0.f, 0.f, 0.f);
            KV[(lcol + 0) * SMS + key] = kv.x;
            KV[(lcol + 1) * SMS + key] = kv.y;
            KV[(lcol + 2) * SMS + key] = kv.z;
            KV[(lcol + 3) * SMS + key] = kv.w;
        }
        __syncthreads();

        float s[4][4] = {};
        #pragma unroll 16
        for (int d = 0; d < 64; d++) {
            const float qa0 = Qs[(r0 + 0) * SMS + d];
            const float qa1 = Qs[(r0 + 1) * SMS + d];
            const float qa2 = Qs[(r0 + 2) * SMS + d];
            const float qa3 = Qs[(r0 + 3) * SMS + d];
            const float4 kb = *(const float4*)&KV[d * SMS + c0];
            s[0][0] += qa0*kb.x; s[0][1] += qa0*kb.y; s[0][2] += qa0*kb.z; s[0][3] += qa0*kb.w;
            s[1][0] += qa1*kb.x; s[1][1] += qa1*kb.y; s[1][2] += qa1*kb.z; s[1][3] += qa1*kb.w;
            s[2][0] += qa2*kb.x; s[2][1] += qa2*kb.y; s[2][2] += qa2*kb.z; s[2][3] += qa2*kb.w;
            s[3][0] += qa3*kb.x; s[3][1] += qa3*kb.y; s[3][2] += qa3*kb.z; s[3][3] += qa3*kb.w;
        }

        const float scale = 0.125f;
        #pragma unroll
        for (int i = 0; i < 4; i++) {
            #pragma unroll
            for (int j = 0; j < 4; j++) {
                s[i][j] *= scale;
                if (c0 + j >= kn) s[i][j] = -1.0e30f;
            }
        }

        #pragma unroll
        for (int i = 0; i < 4; i++) {
            float rm = fmaxf(fmaxf(s[i][0], s[i][1]), fmaxf(s[i][2], s[i][3]));
            #pragma unroll
            for (int o = 8; o >= 1; o >>= 1)
                rm = fmaxf(rm, __shfl_xor_sync(0xffffffffu, rm, o));
            const float mn = fmaxf(m_[i], rm);
            const float al = __expf(m_[i] - mn);
            m_[i] = mn;
            float rs = 0.f;
            #pragma unroll
            for (int j = 0; j < 4; j++) {
                s[i][j] = __expf(s[i][j] - mn);
                rs += s[i][j];
            }
            #pragma unroll
            for (int o = 8; o >= 1; o >>= 1)
                rs += __shfl_xor_sync(0xffffffffu, rs, o);
            l_[i] = l_[i] * al + rs;
            #pragma unroll
            for (int j = 0; j < 4; j++) acc[i][j] *= al;
        }

        __syncthreads();

        #pragma unroll
        for (int i = 0; i < 4; i++)
            #pragma unroll
            for (int j = 0; j < 4; j++)
                Ps[(r0 + i) * SMS + c0 + j] = s[i][j];

        #pragma unroll
        for (int rep = 0; rep < 4; rep++) {
            const int key = rep * 16 + lrow;
            float4 vv = (key < kn) ? *(const float4*)(Vp + (size_t)(k0 + key) * HD + lcol)
                                   : make_float4(0.f, 0.f, 0.f, 0.f);
            *(float4*)&KV[key * SMS + lcol] = vv;
        }
        __syncthreads();

        #pragma unroll 16
        for (int k = 0; k < 64; k++) {
            const float p0 = Ps[(r0 + 0) * SMS + k];
            const float p1 = Ps[(r0 + 1) * SMS + k];
            const float p2 = Ps[(r0 + 2) * SMS + k];
            const float p3 = Ps[(r0 + 3) * SMS + k];
            const float4 vv = *(const float4*)&KV[k * SMS + c0];
            acc[0][0] += p0*vv.x; acc[0][1] += p0*vv.y; acc[0][2] += p0*vv.z; acc[0][3] += p0*vv.w;
            acc[1][0] += p1*vv.x; acc[1][1] += p1*vv.y; acc[1][2] += p1*vv.z; acc[1][3] += p1*vv.w;
            acc[2][0] += p2*vv.x; acc[2][1] += p2*vv.y; acc[2][2] += p2*vv.z; acc[2][3] += p2*vv.w;
            acc[3][0] += p3*vv.x; acc[3][1] += p3*vv.y; acc[3][2] += p3*vv.z; acc[3][3] += p3*vv.w;
        }
    }

    const int b = bh >> 4;
    const int h = bh & 15;
    #pragma unroll
    for (int i = 0; i < 4; i++) {
        const int gn = q0 + r0 + i;
        if (gn < NSEQ) {
            const float inv = 1.0f / l_[i];
            float4 v4 = make_float4(acc[i][0]*inv, acc[i][1]*inv, acc[i][2]*inv, acc[i][3]*inv);
            *(float4*)(g_attn + ((size_t)b * NSEQ + gn) * CDIM + h * HD + c0) = v4;
        }
    }
}

// ---------------------------------------------------------------------------
extern "C" void kernel_launch(void* const* d_in, const int* in_sizes, int n_in,
                              void* d_out, int out_size)
{
    const float* x     = (const float*)d_in[0];
    const float* Wqkv  = (const float*)d_in[1];
    const float* Wproj = (const float*)d_in[2];
    const float* bproj = (const float*)d_in[3];
    float* out = (float*)d_out;

    const int attn_smem = 3 * 64 * SMS * (int)sizeof(float);
    cudaFuncSetAttribute(attn_kernel,
                         cudaFuncAttributeMaxDynamicSharedMemorySize, attn_smem);

    // 1) QKV projection (mma.sync bf16 3-term), scatter into g_q/g_k/g_v
    gemm_mma<0><<<dim3(QKV_OUT / 128, M_TOT / 128), 256>>>(x, Wqkv, nullptr, nullptr);

    // 2) RoPE in place on q, k
    const int rope_total = 2 * NB * NH * NSEQ * 30;
    rope_kernel<<<(rope_total + 255) / 256, 256>>>();

    // 3) Attention -> g_attn [B,N,C]
    attn_kernel<<<dim3(NKT, NB * NH), 256, attn_smem>>>();

    // 4) Output projection + bias -> d_out (mma.sync bf16 3-term)
    gemm_mma<1><<<dim3(CDIM / 128, M_TOT / 128), 256>>>(nullptr, Wproj, bproj, out);
}

// round 9
// speedup vs baseline: 2.3049x; 1.4049x over previous
#include <cuda_runtime.h>
#include <cuda_bf16.h>
#include <math.h>
#include <stdint.h>

// Problem constants
#define NB    4
#define NSEQ  1568
#define CDIM  1024
#define NH    16
#define HD    64
#define M_TOT (NB*NSEQ)          // 6272
#define QKV_OUT (3*CDIM)         // 3072
#define NKT   ((NSEQ+63)/64)     // 25 key tiles
#define NQT   ((NSEQ+127)/128)   // 13 query tiles

// Scratch (device globals — no allocation allowed)
__device__ float g_q[NB*NH*NSEQ*HD];
__device__ float g_k[NB*NH*NSEQ*HD];
__device__ float g_v[NB*NH*NSEQ*HD];
__device__ float g_attn[M_TOT*CDIM];

// ===========================================================================
// Warp-MMA helpers (compute_103-safe: mma.sync + ldmatrix, sm_80 features)
// ===========================================================================
__device__ __forceinline__ uint32_t smem_u32(const void* p) {
    uint32_t a;
    asm("{ .reg .u64 t; cvta.to.shared.u64 t, %1; cvt.u32.u64 %0, t; }"
        : "=r"(a) : "l"(p));
    return a;
}

#define LDMX4(r0, r1, r2, r3, addr) \
    asm volatile("ldmatrix.sync.aligned.m8n8.x4.shared.b16 {%0,%1,%2,%3}, [%4];" \
        : "=r"(r0), "=r"(r1), "=r"(r2), "=r"(r3) : "r"(addr))

#define LDMX4T(r0, r1, r2, r3, addr) \
    asm volatile("ldmatrix.sync.aligned.m8n8.x4.trans.shared.b16 {%0,%1,%2,%3}, [%4];" \
        : "=r"(r0), "=r"(r1), "=r"(r2), "=r"(r3) : "r"(addr))

#define MMA16816(d, a, b0, b1) \
    asm volatile("mma.sync.aligned.m16n8k16.row.col.f32.bf16.bf16.f32 " \
        "{%0,%1,%2,%3}, {%4,%5,%6,%7}, {%8,%9}, {%0,%1,%2,%3};" \
        : "+f"((d)[0]), "+f"((d)[1]), "+f"((d)[2]), "+f"((d)[3]) \
        : "r"((a)[0]), "r"((a)[1]), "r"((a)[2]), "r"((a)[3]), "r"(b0), "r"(b1))

// convert float4 -> 4 bf16 hi (uint2) + 4 bf16 lo (uint2)
__device__ __forceinline__ void cvt4_hl(float4 f, uint2& hi, uint2& lo) {
    float xs[4] = {f.x, f.y, f.z, f.w};
    uint32_t h[2], l[2];
    #pragma unroll
    for (int i = 0; i < 2; i++) {
        float a = xs[2*i], b = xs[2*i+1];
        __nv_bfloat16 ha = __float2bfloat16_rn(a);
        __nv_bfloat16 hb = __float2bfloat16_rn(b);
        float ra = a - __bfloat162float(ha);
        float rb = b - __bfloat162float(hb);
        __nv_bfloat16 la = __float2bfloat16_rn(ra);
        __nv_bfloat16 lb = __float2bfloat16_rn(rb);
        h[i] = (uint32_t)__bfloat16_as_ushort(ha) | ((uint32_t)__bfloat16_as_ushort(hb) << 16);
        l[i] = (uint32_t)__bfloat16_as_ushort(la) | ((uint32_t)__bfloat16_as_ushort(lb) << 16);
    }
    hi = make_uint2(h[0], h[1]);
    lo = make_uint2(l[0], l[1]);
}

__device__ __forceinline__ void pack2_hl(float a, float b, uint32_t& hi, uint32_t& lo) {
    __nv_bfloat16 ha = __float2bfloat16_rn(a);
    __nv_bfloat16 hb = __float2bfloat16_rn(b);
    __nv_bfloat16 la = __float2bfloat16_rn(a - __bfloat162float(ha));
    __nv_bfloat16 lb = __float2bfloat16_rn(b - __bfloat162float(hb));
    hi = (uint32_t)__bfloat16_as_ushort(ha) | ((uint32_t)__bfloat16_as_ushort(hb) << 16);
    lo = (uint32_t)__bfloat16_as_ushort(la) | ((uint32_t)__bfloat16_as_ushort(lb) << 16);
}

// ===========================================================================
// bf16 3-term-split GEMM via mma.sync (unchanged from round 6 — validated)
// ===========================================================================
#define ASTR 24
#define NCH  (CDIM / 16)   // 64 chunks

template<int EPI>
__global__ __launch_bounds__(256, 2)
void gemm_mma(const float* __restrict__ A, const float* __restrict__ W,
              const float* __restrict__ bias, float* __restrict__ out)
{
    __shared__ __align__(16) uint16_t smA[2][2][128 * ASTR];  // [stage][hi/lo]
    __shared__ __align__(16) uint16_t smB[2][2][128 * ASTR];

    const int t    = threadIdx.x;
    const int lane = t & 31;
    const int w    = t >> 5;
    const int warpM = w >> 2;       // 0..1
    const int warpN = w & 3;        // 0..3
    const int m0 = blockIdx.y * 128;
    const int o0 = blockIdx.x * 128;

    const float* Asrc = (EPI == 0) ? A : g_attn;
    const int lrow = t >> 1;          // 0..127
    const int lco  = (t & 1) * 8;     // 0 or 8
    const float* Ap = Asrc + (size_t)(m0 + lrow) * CDIM + lco;
    const float* Wp = W    + (size_t)(o0 + lrow) * CDIM + lco;

    const int aR = warpM * 64;
    const uint32_t aFragOff = (uint32_t)(( (lane & 15) ) * ASTR + (lane >> 4) * 8);
    const uint32_t bRow  = (uint32_t)((lane & 7) + ((lane >> 4) << 3));
    const uint32_t bKoff = (uint32_t)(((lane >> 3) & 1) * 8);
    const int bN = warpN * 32;

    float acc[4][4][4];
    #pragma unroll
    for (int i = 0; i < 4; i++)
        #pragma unroll
        for (int j = 0; j < 4; j++)
            #pragma unroll
            for (int r = 0; r < 4; r++) acc[i][j][r] = 0.f;

    float4 pa0 = *(const float4*)(Ap + 0);
    float4 pa1 = *(const float4*)(Ap + 4);
    float4 pb0 = *(const float4*)(Wp + 0);
    float4 pb1 = *(const float4*)(Wp + 4);

    #pragma unroll 1
    for (int kc = 0; kc < NCH; kc++) {
        const int buf = kc & 1;
        {
            uint2 hi, lo;
            uint16_t* ah = &smA[buf][0][lrow * ASTR + lco];
            uint16_t* al = &smA[buf][1][lrow * ASTR + lco];
            cvt4_hl(pa0, hi, lo);
            *(uint2*)ah = hi;  *(uint2*)al = lo;
            cvt4_hl(pa1, hi, lo);
            *(uint2*)(ah + 4) = hi;  *(uint2*)(al + 4) = lo;

            uint16_t* bh = &smB[buf][0][lrow * ASTR + lco];
            uint16_t* bl = &smB[buf][1][lrow * ASTR + lco];
            cvt4_hl(pb0, hi, lo);
            *(uint2*)bh = hi;  *(uint2*)bl = lo;
            cvt4_hl(pb1, hi, lo);
            *(uint2*)(bh + 4) = hi;  *(uint2*)(bl + 4) = lo;
        }
        __syncthreads();

        if (kc + 1 < NCH) {
            const float* An = Ap + (kc + 1) * 16;
            const float* Wn = Wp + (kc + 1) * 16;
            pa0 = *(const float4*)(An + 0);
            pa1 = *(const float4*)(An + 4);
            pb0 = *(const float4*)(Wn + 0);
            pb1 = *(const float4*)(Wn + 4);
        }

        #pragma unroll
        for (int term = 0; term < 3; term++) {
            const uint16_t* Ab = smA[buf][term == 2 ? 1 : 0];
            const uint16_t* Bb = smB[buf][term == 1 ? 1 : 0];

            uint32_t af[4][4];
            #pragma unroll
            for (int mt = 0; mt < 4; mt++) {
                uint32_t addr = smem_u32(Ab + (aR + mt * 16) * ASTR) + aFragOff * 2;
                LDMX4(af[mt][0], af[mt][1], af[mt][2], af[mt][3], addr);
            }
            uint32_t bf[4][2];
            #pragma unroll
            for (int ntp = 0; ntp < 2; ntp++) {
                uint32_t addr = smem_u32(Bb + (bN + ntp * 16 + bRow) * ASTR + bKoff);
                LDMX4(bf[2*ntp][0], bf[2*ntp][1], bf[2*ntp+1][0], bf[2*ntp+1][1], addr);
            }
            #pragma unroll
            for (int mt = 0; mt < 4; mt++)
                #pragma unroll
                for (int nt = 0; nt < 4; nt++)
                    MMA16816(acc[mt][nt], af[mt], bf[nt][0], bf[nt][1]);
        }
    }

    const int lr = lane >> 2;
    const int lc = (lane & 3) * 2;
    #pragma unroll
    for (int mt = 0; mt < 4; mt++) {
        #pragma unroll
        for (int nt = 0; nt < 4; nt++) {
            const int o = o0 + warpN * 32 + nt * 8 + lc;
            #pragma unroll
            for (int half = 0; half < 2; half++) {
                const int m = m0 + warpM * 64 + mt * 16 + lr + half * 8;
                float2 v = make_float2(acc[mt][nt][half * 2], acc[mt][nt][half * 2 + 1]);
                if (EPI == 0) {
                    const int s  = o >> 10;
                    const int h  = (o >> 6) & 15;
                    const int d0 = o & 63;
                    const int b  = m / NSEQ;
                    const int n  = m - b * NSEQ;
                    float* dst = (s == 0 ? g_q : s == 1 ? g_k : g_v)
                                 + (((size_t)(b * NH + h)) * NSEQ + n) * HD + d0;
                    *(float2*)dst = v;
                } else {
                    v.x += bias[o];
                    v.y += bias[o + 1];
                    *(float2*)(out + (size_t)m * CDIM + o) = v;
                }
            }
        }
    }
}

// ---------------------------------------------------------------------------
// RoPE (unchanged, matches reference's interleaved-pair indexing exactly)
// ---------------------------------------------------------------------------
__global__ void rope_kernel()
{
    const int total = 2 * NB * NH * NSEQ * 30;
    int i = blockIdx.x * blockDim.x + threadIdx.x;
    if (i >= total) return;

    const int p30  = i % 30;
    int rest       = i / 30;
    const int bhn  = rest % (NB * NH * NSEQ);
    const int tsel = rest / (NB * NH * NSEQ);

    const int n  = bhn % NSEQ;
    const int bh = bhn / NSEQ;

    const int a = p30 / 10;
    const int p = p30 % 10;

    const int rem = n % 196;
    float pos;
    if (a == 0)      pos = (float)(n / 196);
    else if (a == 1) pos = (float)(rem / 14);
    else             pos = (float)(rem % 14);

    const int d0 = a * 20 + 2 * p;
    const int f0 = (2 * p) % 10;
    const int f1 = (2 * p + 1) % 10;
    const float LOG1E4 = 9.210340371976184f;
    const float w0 = expf(-(float)f0 * 0.1f * LOG1E4);
    const float w1 = expf(-(float)f1 * 0.1f * LOG1E4);

    float s0, c0, s1, c1;
    sincosf(pos * w0, &s0, &c0);
    sincosf(pos * w1, &s1, &c1);

    float* buf = tsel ? g_k : g_q;
    const size_t base = ((size_t)bh * NSEQ + n) * HD;
    const float x0 = buf[base + d0];
    const float x1 = buf[base + d0 + 1];
    buf[base + d0]     = x0 * c0 - x1 * s0;
    buf[base + d0 + 1] = x1 * c1 + x0 * s1;
}

// ===========================================================================
// Flash attention via mma.sync, bf16 3-term split on BOTH QK^T and PV.
//   CTA = 128 q-rows x one (b,h). 8 warps x 16 q-rows. KT=64 key tiles.
//   Q fragments hoisted; P kept in registers (c-frag == a-frag layout);
//   V via ldmatrix.x4.trans. SMEM row pitch 72 bf16 (conflict-free).
//   Output written to g_attn [B,N,C].
// ===========================================================================
#define QSTR 72
#define ATTN_SMEM ((2*128 + 4*64) * QSTR * 2)   // 73728 B

__global__ __launch_bounds__(256, 1) void attn_mma()
{
    extern __shared__ uint16_t smu[];
    uint16_t* Qh = smu;                   // [128][QSTR]
    uint16_t* Ql = Qh + 128 * QSTR;
    uint16_t* Kh = Ql + 128 * QSTR;       // [64][QSTR]
    uint16_t* Kl = Kh + 64 * QSTR;
    uint16_t* Vh = Kl + 64 * QSTR;
    uint16_t* Vl = Vh + 64 * QSTR;

    const int t    = threadIdx.x;
    const int lane = t & 31;
    const int wid  = t >> 5;
    const int bh   = blockIdx.y;
    const int q0   = blockIdx.x * 128;

    const float* Qp = g_q + (size_t)bh * NSEQ * HD;
    const float* Kp = g_k + (size_t)bh * NSEQ * HD;
    const float* Vp = g_v + (size_t)bh * NSEQ * HD;

    const float4 z4 = make_float4(0.f, 0.f, 0.f, 0.f);

    // ---- load Q tile (hi/lo) ----
    #pragma unroll
    for (int it = 0; it < 8; it++) {
        const int f   = it * 256 + t;      // float4 index over 128x16
        const int row = f >> 4;
        const int c4  = f & 15;
        const int gq  = q0 + row;
        float4 v = (gq < NSEQ) ? *(const float4*)(Qp + (size_t)gq * HD + c4 * 4) : z4;
        uint2 hi, lo;
        cvt4_hl(v, hi, lo);
        *(uint2*)&Qh[row * QSTR + c4 * 4] = hi;
        *(uint2*)&Ql[row * QSTR + c4 * 4] = lo;
    }
    __syncthreads();

    // ---- hoist Q fragments (4 k-chunks x 4 regs, hi+lo) ----
    uint32_t qh[4][4], ql[4][4];
    {
        const int aRow = wid * 16 + (lane & 15);
        const int aCol = (lane >> 4) * 8;
        #pragma unroll
        for (int kc = 0; kc < 4; kc++) {
            uint32_t ad = smem_u32(&Qh[aRow * QSTR + kc * 16 + aCol]);
            LDMX4(qh[kc][0], qh[kc][1], qh[kc][2], qh[kc][3], ad);
            ad = smem_u32(&Ql[aRow * QSTR + kc * 16 + aCol]);
            LDMX4(ql[kc][0], ql[kc][1], ql[kc][2], ql[kc][3], ad);
        }
    }

    float oacc[8][4];
    #pragma unroll
    for (int i = 0; i < 8; i++)
        #pragma unroll
        for (int j = 0; j < 4; j++) oacc[i][j] = 0.f;
    float m0v = -3.0e38f, m1v = -3.0e38f, l0 = 0.f, l1 = 0.f;

    const int bRow = (lane & 7) + ((lane >> 4) << 3);
    const int bK   = ((lane >> 3) & 1) * 8;
    const int vRow = (lane & 7) + (lane & 8);
    const int vCol = ((lane >> 4) << 3);

    #pragma unroll 1
    for (int kt = 0; kt < NKT; kt++) {
        const int k0 = kt * 64;
        __syncthreads();   // previous tile fully consumed
        // ---- load K,V tiles (hi/lo) ----
        #pragma unroll
        for (int it = 0; it < 4; it++) {
            const int f   = it * 256 + t;  // float4 index over 64x16
            const int row = f >> 4;
            const int c4  = f & 15;
            const int gk  = k0 + row;
            const bool ok = (gk < NSEQ);
            float4 kv = ok ? *(const float4*)(Kp + (size_t)gk * HD + c4 * 4) : z4;
            uint2 hi, lo;
            cvt4_hl(kv, hi, lo);
            *(uint2*)&Kh[row * QSTR + c4 * 4] = hi;
            *(uint2*)&Kl[row * QSTR + c4 * 4] = lo;
            float4 vv = ok ? *(const float4*)(Vp + (size_t)gk * HD + c4 * 4) : z4;
            cvt4_hl(vv, hi, lo);
            *(uint2*)&Vh[row * QSTR + c4 * 4] = hi;
            *(uint2*)&Vl[row * QSTR + c4 * 4] = lo;
        }
        __syncthreads();

        // ---- S = Q K^T (3-term split) ----
        float s[8][4];
        #pragma unroll
        for (int i = 0; i < 8; i++)
            #pragma unroll
            for (int j = 0; j < 4; j++) s[i][j] = 0.f;

        #pragma unroll
        for (int np = 0; np < 4; np++) {
            #pragma unroll
            for (int kc = 0; kc < 4; kc++) {
                uint32_t kh0, kh1, kh2, kh3, kl0, kl1, kl2, kl3;
                uint32_t ad = smem_u32(&Kh[(np * 16 + bRow) * QSTR + kc * 16 + bK]);
                LDMX4(kh0, kh1, kh2, kh3, ad);
                ad = smem_u32(&Kl[(np * 16 + bRow) * QSTR + kc * 16 + bK]);
                LDMX4(kl0, kl1, kl2, kl3, ad);
                MMA16816(s[2*np],   qh[kc], kh0, kh1);
                MMA16816(s[2*np],   qh[kc], kl0, kl1);
                MMA16816(s[2*np],   ql[kc], kh0, kh1);
                MMA16816(s[2*np+1], qh[kc], kh2, kh3);
                MMA16816(s[2*np+1], qh[kc], kl2, kl3);
                MMA16816(s[2*np+1], ql[kc], kh2, kh3);
            }
        }

        // ---- online softmax ----
        const float scale = 0.125f;
        float rmax0 = -3.0e38f, rmax1 = -3.0e38f;
        const bool last = (kt == NKT - 1);
        #pragma unroll
        for (int nt = 0; nt < 8; nt++) {
            #pragma unroll
            for (int j = 0; j < 2; j++) {
                s[nt][j]     *= scale;
                s[nt][j + 2] *= scale;
                if (last) {
                    const int col = k0 + nt * 8 + (lane & 3) * 2 + j;
                    if (col >= NSEQ) { s[nt][j] = -1.0e30f; s[nt][j + 2] = -1.0e30f; }
                }
                rmax0 = fmaxf(rmax0, s[nt][j]);
                rmax1 = fmaxf(rmax1, s[nt][j + 2]);
            }
        }
        rmax0 = fmaxf(rmax0, __shfl_xor_sync(0xffffffffu, rmax0, 1));
        rmax0 = fmaxf(rmax0, __shfl_xor_sync(0xffffffffu, rmax0, 2));
        rmax1 = fmaxf(rmax1, __shfl_xor_sync(0xffffffffu, rmax1, 1));
        rmax1 = fmaxf(rmax1, __shfl_xor_sync(0xffffffffu, rmax1, 2));

        const float mn0 = fmaxf(m0v, rmax0);
        const float mn1 = fmaxf(m1v, rmax1);
        const float al0 = __expf(m0v - mn0);
        const float al1 = __expf(m1v - mn1);
        m0v = mn0; m1v = mn1;

        float rs0 = 0.f, rs1 = 0.f;
        #pragma unroll
        for (int nt = 0; nt < 8; nt++) {
            #pragma unroll
            for (int j = 0; j < 2; j++) {
                s[nt][j]     = __expf(s[nt][j]     - mn0);
                s[nt][j + 2] = __expf(s[nt][j + 2] - mn1);
                rs0 += s[nt][j];
                rs1 += s[nt][j + 2];
            }
        }
        rs0 += __shfl_xor_sync(0xffffffffu, rs0, 1);
        rs0 += __shfl_xor_sync(0xffffffffu, rs0, 2);
        rs1 += __shfl_xor_sync(0xffffffffu, rs1, 1);
        rs1 += __shfl_xor_sync(0xffffffffu, rs1, 2);
        l0 = l0 * al0 + rs0;
        l1 = l1 * al1 + rs1;

        #pragma unroll
        for (int nt = 0; nt < 8; nt++) {
            oacc[nt][0] *= al0; oacc[nt][1] *= al0;
            oacc[nt][2] *= al1; oacc[nt][3] *= al1;
        }

        // ---- P -> bf16 hi/lo A-fragments (register-only) ----
        uint32_t ph[4][4], pl[4][4];
        #pragma unroll
        for (int kc = 0; kc < 4; kc++) {
            pack2_hl(s[2*kc][0],   s[2*kc][1],   ph[kc][0], pl[kc][0]);
            pack2_hl(s[2*kc][2],   s[2*kc][3],   ph[kc][1], pl[kc][1]);
            pack2_hl(s[2*kc+1][0], s[2*kc+1][1], ph[kc][2], pl[kc][2]);
            pack2_hl(s[2*kc+1][2], s[2*kc+1][3], ph[kc][3], pl[kc][3]);
        }

        // ---- O += P V (3-term split), V via ldmatrix.trans ----
        #pragma unroll
        for (int dp = 0; dp < 4; dp++) {
            #pragma unroll
            for (int kc = 0; kc < 4; kc++) {
                uint32_t vh0, vh1, vh2, vh3, vl0, vl1, vl2, vl3;
                uint32_t ad = smem_u32(&Vh[(kc * 16 + vRow) * QSTR + dp * 16 + vCol]);
                LDMX4T(vh0, vh1, vh2, vh3, ad);
                ad = smem_u32(&Vl[(kc * 16 + vRow) * QSTR + dp * 16 + vCol]);
                LDMX4T(vl0, vl1, vl2, vl3, ad);
                MMA16816(oacc[2*dp],   ph[kc], vh0, vh1);
                MMA16816(oacc[2*dp],   ph[kc], vl0, vl1);
                MMA16816(oacc[2*dp],   pl[kc], vh0, vh1);
                MMA16816(oacc[2*dp+1], ph[kc], vh2, vh3);
                MMA16816(oacc[2*dp+1], ph[kc], vl2, vl3);
                MMA16816(oacc[2*dp+1], pl[kc], vh2, vh3);
            }
        }
    }

    // ---- epilogue: normalize + store to g_attn [B,N,C] ----
    const float inv0 = 1.0f / l0;
    const float inv1 = 1.0f / l1;
    const int b = bh >> 4;
    const int h = bh & 15;
    const int r0g = q0 + wid * 16 + (lane >> 2);
    #pragma unroll
    for (int nt = 0; nt < 8; nt++) {
        const int d = h * HD + nt * 8 + (lane & 3) * 2;
        if (r0g < NSEQ) {
            float2 v = make_float2(oacc[nt][0] * inv0, oacc[nt][1] * inv0);
            *(float2*)(g_attn + ((size_t)b * NSEQ + r0g) * CDIM + d) = v;
        }
        if (r0g + 8 < NSEQ) {
            float2 v = make_float2(oacc[nt][2] * inv1, oacc[nt][3] * inv1);
            *(float2*)(g_attn + ((size_t)b * NSEQ + r0g + 8) * CDIM + d) = v;
        }
    }
}

// ---------------------------------------------------------------------------
extern "C" void kernel_launch(void* const* d_in, const int* in_sizes, int n_in,
                              void* d_out, int out_size)
{
    const float* x     = (const float*)d_in[0];
    const float* Wqkv  = (const float*)d_in[1];
    const float* Wproj = (const float*)d_in[2];
    const float* bproj = (const float*)d_in[3];
    float* out = (float*)d_out;

    cudaFuncSetAttribute(attn_mma,
                         cudaFuncAttributeMaxDynamicSharedMemorySize, ATTN_SMEM);

    // 1) QKV projection (mma.sync bf16 3-term), scatter into g_q/g_k/g_v
    gemm_mma<0><<<dim3(QKV_OUT / 128, M_TOT / 128), 256>>>(x, Wqkv, nullptr, nullptr);

    // 2) RoPE in place on q, k
    const int rope_total = 2 * NB * NH * NSEQ * 30;
    rope_kernel<<<(rope_total + 255) / 256, 256>>>();

    // 3) Attention (mma.sync, split precision) -> g_attn [B,N,C]
    attn_mma<<<dim3(NQT, NB * NH), 256, ATTN_SMEM>>>();

    // 4) Output projection + bias -> d_out (mma.sync bf16 3-term)
    gemm_mma<1><<<dim3(CDIM / 128, M_TOT / 128), 256>>>(nullptr, Wproj, bproj, out);
}